// round 3
// baseline (speedup 1.0000x reference)
#include <cuda_runtime.h>
#include <cstdint>

#define H_DIM 1024
#define I_DIM 2816
#define E_NUM 8
#define T_NUM 2048
#define SLOTS (T_NUM * 2)   // 4096 (every token has exactly 2 experts)

// ---------------- scratch (static __device__, allocation-free) ----------------
__device__ float g_gbuf[SLOTS * I_DIM];   // gate GEMM out, then h = silu(g)*u in place
__device__ float g_ubuf[SLOTS * I_DIM];   // up GEMM out
__device__ float g_ybuf[SLOTS * H_DIM];   // down GEMM out (per-assignment)
__device__ int   g_counts[E_NUM];
__device__ int   g_offsets[E_NUM];
__device__ int   g_fill[E_NUM];
__device__ int   g_slot_token[SLOTS];     // slot -> token
__device__ int   g_token_slot[SLOTS];     // (token,k) -> slot
__device__ float g_token_wt[SLOTS];       // (token,k) -> routing weight
__device__ int   g_token_eid[SLOTS];      // (token,k) -> expert

__device__ __forceinline__ float to_tf32(float x) {
    float r;
    asm("cvt.rna.tf32.f32 %0, %1;" : "=f"(r) : "f"(x));
    return r;
}

__device__ __forceinline__ void mma_tf32(float c[4], const uint32_t a[4], const uint32_t b[2]) {
    asm volatile(
        "mma.sync.aligned.m16n8k8.row.col.f32.tf32.tf32.f32 "
        "{%0,%1,%2,%3}, {%4,%5,%6,%7}, {%8,%9}, {%0,%1,%2,%3};\n"
        : "+f"(c[0]), "+f"(c[1]), "+f"(c[2]), "+f"(c[3])
        : "r"(a[0]), "r"(a[1]), "r"(a[2]), "r"(a[3]), "r"(b[0]), "r"(b[1]));
}

// ---------------- pipeline kernels ----------------

__global__ void init_kernel() {
    if (threadIdx.x < E_NUM) g_counts[threadIdx.x] = 0;
}

// one warp per token: 8 router dots (fp32 exact), softmax, top-2
__global__ void router_kernel(const float* __restrict__ x, const float* __restrict__ rw) {
    __shared__ float s_rw[E_NUM * H_DIM];  // 32 KB
    int tid = threadIdx.x;
    for (int i = tid; i < E_NUM * H_DIM; i += blockDim.x) s_rw[i] = rw[i];
    __syncthreads();
    int wid = tid >> 5, lane = tid & 31;
    int t = blockIdx.x * 8 + wid;
    const float* xr = x + (size_t)t * H_DIM;
    float acc[E_NUM];
#pragma unroll
    for (int e = 0; e < E_NUM; e++) acc[e] = 0.f;
    for (int h = lane; h < H_DIM; h += 32) {
        float xv = xr[h];
#pragma unroll
        for (int e = 0; e < E_NUM; e++) acc[e] += xv * s_rw[e * H_DIM + h];
    }
#pragma unroll
    for (int e = 0; e < E_NUM; e++) {
#pragma unroll
        for (int o = 16; o > 0; o >>= 1) acc[e] += __shfl_xor_sync(0xffffffff, acc[e], o);
    }
    if (lane == 0) {
        float m = acc[0];
#pragma unroll
        for (int e = 1; e < E_NUM; e++) m = fmaxf(m, acc[e]);
        float p[E_NUM], s = 0.f;
#pragma unroll
        for (int e = 0; e < E_NUM; e++) { p[e] = expf(acc[e] - m); s += p[e]; }
        float inv = 1.f / s;
        int i0 = 0; float v0 = p[0];
#pragma unroll
        for (int e = 1; e < E_NUM; e++) if (p[e] > v0) { v0 = p[e]; i0 = e; }
        int i1 = -1; float v1 = -1.f;
#pragma unroll
        for (int e = 0; e < E_NUM; e++) if (e != i0 && p[e] > v1) { v1 = p[e]; i1 = e; }
        g_token_eid[t * 2 + 0] = i0;
        g_token_eid[t * 2 + 1] = i1;
        g_token_wt[t * 2 + 0] = v0 * inv;
        g_token_wt[t * 2 + 1] = v1 * inv;
        atomicAdd(&g_counts[i0], 1);
        atomicAdd(&g_counts[i1], 1);
    }
}

__global__ void scan_kernel() {
    int off = 0;
    for (int e = 0; e < E_NUM; e++) {
        g_offsets[e] = off;
        g_fill[e] = off;
        off += g_counts[e];
    }
}

__global__ void scatter_kernel() {
    int i = blockIdx.x * blockDim.x + threadIdx.x;
    if (i >= SLOTS) return;
    int e = g_token_eid[i];
    int slot = atomicAdd(&g_fill[e], 1);
    g_slot_token[slot] = i >> 1;
    g_token_slot[i] = slot;
}

// TN GEMM: C[m,n] = sum_k A[m,k] * B[e][n,k], tf32 mma, per-expert grouped.
// MODE 0: gate (A = x gathered via slot_token, C = g_gbuf)
// MODE 1: up   (A = x gathered via slot_token, C = g_ubuf)
// MODE 2: down (A = g_gbuf slot rows,          C = g_ybuf)
template <int KDIM, int MODE>
__global__ __launch_bounds__(256, 1)
void gemm_tn_kernel(const float* __restrict__ X,
                    const float* __restrict__ Bfull,
                    int NDIM) {
    constexpr int BM = 128, BN = 128, BK = 32;
    constexpr int SK = BK + 4;  // 36 floats: conflict-free frag loads + vec4 ldg stage
    __shared__ float sA[BM][SK];
    __shared__ float sB[BN][SK];

    const float* A = (MODE == 2) ? (const float*)g_gbuf : X;
    float* C = (MODE == 0) ? g_gbuf : (MODE == 1) ? g_ubuf : g_ybuf;
    const int ldc = NDIM;

    const int e   = blockIdx.z;
    const int cnt = g_counts[e];
    const int off = g_offsets[e];
    const int m0  = blockIdx.x * BM;
    if (m0 >= cnt) return;
    const int n0  = blockIdx.y * BN;

    const int tid  = threadIdx.x;
    const int wid  = tid >> 5;
    const int lane = tid & 31;
    const int wm   = wid >> 2;   // 0..1 (64 rows each)
    const int wn   = wid & 3;    // 0..3 (32 cols each)
    const int g    = lane >> 2;  // 0..7
    const int tig  = lane & 3;   // 0..3

    const float* Bw = Bfull + (size_t)e * NDIM * KDIM + (size_t)n0 * KDIM;

    // per-thread staging: 4 float4 per tile for each of A,B
    const float* aptr[4];
    const float* bptr[4];
#pragma unroll
    for (int i = 0; i < 4; i++) {
        int f = tid + i * 256;        // 0..1023
        int r = f >> 3;               // row 0..127
        int kc = (f & 7) * 4;         // k-col 0..28
        int mi = m0 + r;
        int grow;
        if (MODE != 2) {
            grow = (mi < cnt) ? g_slot_token[off + mi] : g_slot_token[off];
        } else {
            grow = (mi < cnt) ? (off + mi) : off;
        }
        aptr[i] = A + (size_t)grow * KDIM + kc;
        bptr[i] = Bw + (size_t)r * KDIM + kc;
    }

    float4 ra[4], rb[4];
#pragma unroll
    for (int i = 0; i < 4; i++) {
        ra[i] = *(const float4*)aptr[i];
        rb[i] = *(const float4*)bptr[i];
        aptr[i] += BK; bptr[i] += BK;
    }

    auto stage = [&]() {
#pragma unroll
        for (int i = 0; i < 4; i++) {
            int f = tid + i * 256;
            int r = f >> 3;
            int kc = (f & 7) * 4;
            sA[r][kc + 0] = to_tf32(ra[i].x);
            sA[r][kc + 1] = to_tf32(ra[i].y);
            sA[r][kc + 2] = to_tf32(ra[i].z);
            sA[r][kc + 3] = to_tf32(ra[i].w);
            sB[r][kc + 0] = to_tf32(rb[i].x);
            sB[r][kc + 1] = to_tf32(rb[i].y);
            sB[r][kc + 2] = to_tf32(rb[i].z);
            sB[r][kc + 3] = to_tf32(rb[i].w);
        }
    };
    stage();
    __syncthreads();

    float c[4][4][4];
#pragma unroll
    for (int mt = 0; mt < 4; mt++)
#pragma unroll
        for (int nt = 0; nt < 4; nt++)
#pragma unroll
            for (int j = 0; j < 4; j++) c[mt][nt][j] = 0.f;

    constexpr int KT = KDIM / BK;
    for (int kt = 0; kt < KT; kt++) {
        if (kt + 1 < KT) {
#pragma unroll
            for (int i = 0; i < 4; i++) {
                ra[i] = *(const float4*)aptr[i];
                rb[i] = *(const float4*)bptr[i];
                aptr[i] += BK; bptr[i] += BK;
            }
        }
#pragma unroll
        for (int ks = 0; ks < 4; ks++) {
            int kk = ks * 8;
            uint32_t af[4][4], bf[4][2];
#pragma unroll
            for (int mt = 0; mt < 4; mt++) {
                int m = wm * 64 + mt * 16;
                af[mt][0] = __float_as_uint(sA[m + g][kk + tig]);
                af[mt][1] = __float_as_uint(sA[m + g + 8][kk + tig]);
                af[mt][2] = __float_as_uint(sA[m + g][kk + tig + 4]);
                af[mt][3] = __float_as_uint(sA[m + g + 8][kk + tig + 4]);
            }
#pragma unroll
            for (int nt = 0; nt < 4; nt++) {
                int n = wn * 32 + nt * 8;
                bf[nt][0] = __float_as_uint(sB[n + g][kk + tig]);
                bf[nt][1] = __float_as_uint(sB[n + g][kk + tig + 4]);
            }
#pragma unroll
            for (int mt = 0; mt < 4; mt++)
#pragma unroll
                for (int nt = 0; nt < 4; nt++)
                    mma_tf32(c[mt][nt], af[mt], bf[nt]);
        }
        __syncthreads();
        if (kt + 1 < KT) {
            stage();
            __syncthreads();
        }
    }

    // epilogue: rows (g, g+8) per mma tile, cols 2*tig, 2*tig+1
    const int cntloc = cnt - m0;
#pragma unroll
    for (int mt = 0; mt < 4; mt++) {
        int rb0 = wm * 64 + mt * 16 + g;
#pragma unroll
        for (int nt = 0; nt < 4; nt++) {
            int col = n0 + wn * 32 + nt * 8 + 2 * tig;
            if (rb0 < cntloc) {
                float* p = C + (size_t)(off + m0 + rb0) * ldc + col;
                p[0] = c[mt][nt][0];
                p[1] = c[mt][nt][1];
            }
            if (rb0 + 8 < cntloc) {
                float* p = C + (size_t)(off + m0 + rb0 + 8) * ldc + col;
                p[0] = c[mt][nt][2];
                p[1] = c[mt][nt][3];
            }
        }
    }
}

__global__ void silu_mul_kernel() {
    int i = blockIdx.x * blockDim.x + threadIdx.x;
    constexpr int total4 = SLOTS * I_DIM / 4;
    if (i >= total4) return;
    float4 gv = ((const float4*)g_gbuf)[i];
    float4 uv = ((const float4*)g_ubuf)[i];
    float4 o;
    o.x = gv.x / (1.f + expf(-gv.x)) * uv.x;
    o.y = gv.y / (1.f + expf(-gv.y)) * uv.y;
    o.z = gv.z / (1.f + expf(-gv.z)) * uv.z;
    o.w = gv.w / (1.f + expf(-gv.w)) * uv.w;
    ((float4*)g_gbuf)[i] = o;
}

__global__ void combine_kernel(float* __restrict__ out) {
    int i = blockIdx.x * blockDim.x + threadIdx.x;
    constexpr int total4 = T_NUM * H_DIM / 4;
    if (i >= total4) return;
    int t  = i / (H_DIM / 4);
    int c4 = i % (H_DIM / 4);
    int s0 = g_token_slot[t * 2 + 0];
    int s1 = g_token_slot[t * 2 + 1];
    float w0 = g_token_wt[t * 2 + 0];
    float w1 = g_token_wt[t * 2 + 1];
    float4 a = ((const float4*)(g_ybuf + (size_t)s0 * H_DIM))[c4];
    float4 b = ((const float4*)(g_ybuf + (size_t)s1 * H_DIM))[c4];
    float4 o;
    o.x = w0 * a.x + w1 * b.x;
    o.y = w0 * a.y + w1 * b.y;
    o.z = w0 * a.z + w1 * b.z;
    o.w = w0 * a.w + w1 * b.w;
    ((float4*)out)[i] = o;
}

// ---------------- launch ----------------
extern "C" void kernel_launch(void* const* d_in, const int* in_sizes, int n_in,
                              void* d_out, int out_size) {
    const float* x  = (const float*)d_in[0];   // [2048,1024] (2,1024,1024 flattened)
    const float* rw = (const float*)d_in[1];   // [8,1024]
    const float* gw = (const float*)d_in[2];   // [8,2816,1024]
    const float* uw = (const float*)d_in[3];   // [8,2816,1024]
    const float* dw = (const float*)d_in[4];   // [8,1024,2816]
    float* out = (float*)d_out;                // [2048,1024]

    init_kernel<<<1, 32>>>();
    router_kernel<<<T_NUM / 8, 256>>>(x, rw);
    scan_kernel<<<1, 1>>>();
    scatter_kernel<<<(SLOTS + 255) / 256, 256>>>();

    // gate and up: M grouped by expert (gathered token rows), N = 2816, K = 1024
    gemm_tn_kernel<H_DIM, 0><<<dim3(16, I_DIM / 128, E_NUM), 256>>>(x, gw, I_DIM);
    gemm_tn_kernel<H_DIM, 1><<<dim3(16, I_DIM / 128, E_NUM), 256>>>(x, uw, I_DIM);

    silu_mul_kernel<<<(SLOTS * I_DIM / 4 + 255) / 256, 256>>>();

    // down: M = slot rows (no gather), N = 1024, K = 2816
    gemm_tn_kernel<I_DIM, 2><<<dim3(16, H_DIM / 128, E_NUM), 256>>>(nullptr, dw, H_DIM);

    combine_kernel<<<(T_NUM * H_DIM / 4 + 255) / 256, 256>>>(out);
}